// round 3
// baseline (speedup 1.0000x reference)
#include <cuda_runtime.h>
#include <math.h>

#define BBATCH 32
#define LSEQ   1024
#define HDIM   256
#define NROWS  (BBATCH * LSEQ)      // 32768
#define NH     (NROWS * HDIM)       // 8388608
#define EPSV   1e-3f

typedef unsigned long long ull;

// ---------------- scratch (__device__ globals; allocation is forbidden) ----------------
__device__ float g_h[2][NH];
__device__ float g_c[2][NH];
__device__ float g_emb[NH];
__device__ float g_E[NROWS * 1536];
__device__ float g_PRE[NROWS * 1536];
__device__ float g_GFp[NH];
__device__ float g_GF[NH];
__device__ float g_Wcat[768 * 1536];
__device__ float g_Wxp[256 * 1536];
__device__ float g_dh[2][BBATCH * HDIM];
__device__ float g_dc[2][BBATCH * HDIM];
__device__ float g_comb[BBATCH * HDIM];
__device__ float g_gd[BBATCH * HDIM];
__device__ float g_gi[BBATCH * HDIM];
__device__ float g_go[BBATCH * HDIM];
__device__ float g_tln[BBATCH * HDIM];
__device__ float g_Bfx[BBATCH * HDIM];
__device__ float g_Bd[BBATCH * 1536];
__device__ float g_p1[BBATCH * 8 * HDIM];
__device__ float g_p2[BBATCH * 8 * HDIM];
__device__ float g_cp[BBATCH * 8 * HDIM];

// ---------------- helpers ----------------
__device__ __forceinline__ ull pack2(float lo, float hi) {
    ull r;
    asm("mov.b64 %0, {%1, %2};" : "=l"(r) : "f"(lo), "f"(hi));
    return r;
}
__device__ __forceinline__ float2 unpack2(ull v) {
    float lo, hi;
    asm("mov.b64 {%0, %1}, %2;" : "=f"(lo), "=f"(hi) : "l"(v));
    return make_float2(lo, hi);
}
__device__ __forceinline__ ull ffma2(ull a, ull b, ull c) {
    ull d;
    asm("fma.rn.f32x2 %0, %1, %2, %3;" : "=l"(d) : "l"(a), "l"(b), "l"(c));
    return d;
}
__device__ __forceinline__ float sigf(float x) { return 1.f / (1.f + __expf(-x)); }

// block-wide (256 threads) sum of two values
__device__ __forceinline__ float2 blk_reduce2(float a, float b) {
    __shared__ float sA[8], sB[8];
    int lane = threadIdx.x & 31, w = threadIdx.x >> 5;
#pragma unroll
    for (int o = 16; o; o >>= 1) {
        a += __shfl_xor_sync(0xffffffffu, a, o);
        b += __shfl_xor_sync(0xffffffffu, b, o);
    }
    __syncthreads();
    if (lane == 0) { sA[w] = a; sB[w] = b; }
    __syncthreads();
    float ra = 0.f, rb = 0.f;
#pragma unroll
    for (int i = 0; i < 8; i++) { ra += sA[i]; rb += sB[i]; }
    return make_float2(ra, rb);
}

// ---------------- prep: masked inputs ----------------
__global__ void prep_k(const float* __restrict__ word, const float* __restrict__ h0,
                       const float* __restrict__ c0, const float* __restrict__ mask,
                       float* __restrict__ emb, float* __restrict__ h, float* __restrict__ c) {
    int i4 = blockIdx.x * blockDim.x + threadIdx.x;     // over NH/4
    if (i4 >= NH / 4) return;
    float m = mask[i4 >> 6];                             // 64 float4 per row
    float4 w = ((const float4*)word)[i4];
    float4 a = ((const float4*)h0)[i4];
    float4 b = ((const float4*)c0)[i4];
    w.x *= m; w.y *= m; w.z *= m; w.w *= m;
    a.x *= m; a.y *= m; a.z *= m; a.w *= m;
    b.x *= m; b.y *= m; b.z *= m; b.w *= m;
    ((float4*)emb)[i4] = w;
    ((float4*)h)[i4]   = a;
    ((float4*)c)[i4]   = b;
}

// ---------------- column mean over L (two-stage) ----------------
__global__ void colpart_k(const float* __restrict__ X, float* __restrict__ part) {
    int b = blockIdx.x, s = blockIdx.y, c = threadIdx.x;
    float acc = 0.f;
    int rbase = (b << 10) + s * 128;
#pragma unroll 4
    for (int j = 0; j < 128; j++) acc += X[(size_t)(rbase + j) * HDIM + c];
    part[(b * 8 + s) * HDIM + c] = acc;
}
__global__ void colfin_k(const float* __restrict__ part, float* __restrict__ out) {
    int b = blockIdx.x, c = threadIdx.x;
    float a = 0.f;
#pragma unroll
    for (int s = 0; s < 8; s++) a += part[(b * 8 + s) * HDIM + c];
    out[b * HDIM + c] = a * (1.f / 1024.f);
}

// ---------------- weight packing ----------------
__global__ void pack_wcat_k(const float* __restrict__ Wh_g, const float* __restrict__ Wi_g) {
    int idx = blockIdx.x * 256 + threadIdx.x;            // 768*1536
    if (idx >= 768 * 1536) return;
    int kk = idx / 1536, col = idx - kk * 1536;
    int g = col >> 8, c = col & 255;
    float v = (kk < 512) ? Wh_g[g * 131072 + kk * 256 + c]
                         : Wi_g[g * 65536 + (kk - 512) * 256 + c];
    g_Wcat[idx] = v;
}
__global__ void pack_wx_k(const float* __restrict__ Wx_g) {
    int idx = blockIdx.x * 256 + threadIdx.x;            // 256*1536
    if (idx >= 256 * 1536) return;
    int k = idx / 1536, col = idx - k * 1536;
    int g = col >> 8, c = col & 255;
    g_Wxp[idx] = Wx_g[g * 65536 + k * 256 + c];
}

// ---------------- GEMM: C[N x cols] = A(+taps) @ Bw[K x cols] + extras ----------------
// TAPS: K=768; k in [0,256): A row n-1; [256,512): n+1; [512,768): n  (0 at seq edges)
// epilogue: C = acc + Cadd[n][col] + colbias[col] + mask[n]*pbias[b][col]
template <bool TAPS>
__global__ __launch_bounds__(256, 2) void gemm_k(
    const float* __restrict__ A, const float* __restrict__ Bw,
    const float* __restrict__ Cadd, const float* __restrict__ colbias,
    const float* __restrict__ pbias, const float* __restrict__ mask,
    float* __restrict__ C, int cols, int K) {
    __shared__ float As[16][132];
    __shared__ float Bs[16][128];
    const int tid = threadIdx.x;
    const int rowBase = blockIdx.y * 128;
    const int colBase = blockIdx.x * 128;
    const int m0 = (tid >> 4) * 4;
    const int n0 = (tid & 15) * 4;

    ull acc[8][4];
#pragma unroll
    for (int i = 0; i < 8; i++)
#pragma unroll
        for (int j = 0; j < 4; j++) acc[i][j] = 0ULL;

    const int nkt = K >> 4;
    for (int kt = 0; kt < nkt; ++kt) {
        const int tap = TAPS ? (kt >> 4) : 2;
        const int chanBase = TAPS ? ((kt * 16) & 255) : (kt * 16);
        // load A tile (transpose to As[k][m])
#pragma unroll
        for (int i = 0; i < 2; ++i) {
            int idx = tid + i * 256;
            int m = idx >> 2;
            int k4 = (idx & 3) * 4;
            int r = rowBase + m;
            int l = r & 1023;
            float4 v = make_float4(0.f, 0.f, 0.f, 0.f);
            bool ok = (tap == 0) ? (l > 0) : ((tap == 1) ? (l < 1023) : true);
            if (ok) {
                int src = r + ((tap == 0) ? -1 : ((tap == 1) ? 1 : 0));
                v = *(const float4*)(A + (size_t)src * HDIM + chanBase + k4);
            }
            As[k4 + 0][m] = v.x; As[k4 + 1][m] = v.y;
            As[k4 + 2][m] = v.z; As[k4 + 3][m] = v.w;
        }
        // load B tile
#pragma unroll
        for (int i = 0; i < 2; ++i) {
            int idx = tid + i * 256;
            int kr = idx >> 5;
            int c4 = (idx & 31) * 4;
            float4 v = *(const float4*)(Bw + (size_t)(kt * 16 + kr) * cols + colBase + c4);
            *(float4*)&Bs[kr][c4] = v;
        }
        __syncthreads();
#pragma unroll
        for (int k = 0; k < 16; ++k) {
            float4 a0 = *(const float4*)&As[k][m0];
            float4 a1 = *(const float4*)&As[k][m0 + 64];
            float4 b0 = *(const float4*)&Bs[k][n0];
            float4 b1 = *(const float4*)&Bs[k][n0 + 64];
            ull bp0 = pack2(b0.x, b0.y), bp1 = pack2(b0.z, b0.w);
            ull bp2 = pack2(b1.x, b1.y), bp3 = pack2(b1.z, b1.w);
            float av[8] = {a0.x, a0.y, a0.z, a0.w, a1.x, a1.y, a1.z, a1.w};
#pragma unroll
            for (int mi = 0; mi < 8; ++mi) {
                ull ap = pack2(av[mi], av[mi]);
                acc[mi][0] = ffma2(ap, bp0, acc[mi][0]);
                acc[mi][1] = ffma2(ap, bp1, acc[mi][1]);
                acc[mi][2] = ffma2(ap, bp2, acc[mi][2]);
                acc[mi][3] = ffma2(ap, bp3, acc[mi][3]);
            }
        }
        __syncthreads();
    }
    // epilogue
#pragma unroll
    for (int mi = 0; mi < 8; ++mi) {
        int r = rowBase + m0 + ((mi < 4) ? mi : 64 + mi - 4);
        size_t rowoff = (size_t)r * cols;
        int bb = r >> 10;
        float mk = mask[r];
#pragma unroll
        for (int p = 0; p < 4; ++p) {
            int col = colBase + n0 + ((p < 2) ? 2 * p : 64 + 2 * (p - 2));
            float2 v = unpack2(acc[mi][p]);
            float e0 = 0.f, e1 = 0.f;
            if (Cadd)    { e0 += Cadd[rowoff + col];       e1 += Cadd[rowoff + col + 1]; }
            if (colbias) { e0 += colbias[col];             e1 += colbias[col + 1]; }
            if (pbias)   { e0 += mk * pbias[bb * cols + col]; e1 += mk * pbias[bb * cols + col + 1]; }
            float2 o = make_float2(v.x + e0, v.y + e1);
            *(float2*)(C + rowoff + col) = o;
        }
    }
}

// ---------------- sentence-level gates: gd / gi / go ----------------
__global__ void small_gates_k(const float* __restrict__ dh, const float* __restrict__ se,
                              const float* __restrict__ comb, const float* __restrict__ gWx,
                              const float* __restrict__ gWg, const float* __restrict__ gWh,
                              const float* __restrict__ gb, const float* __restrict__ ln_a,
                              const float* __restrict__ ln_b) {
    int b = blockIdx.x, g = blockIdx.y, c = threadIdx.x;
    __shared__ float sx[256], ss[256], sc[256];
    sx[c] = dh[b * 256 + c];
    ss[c] = se[b * 256 + c];
    sc[c] = comb[b * 256 + c];
    __syncthreads();
    const float* Wx = gWx + g * 65536;
    const float* Wg = gWg + g * 65536;
    const float* Wh = gWh + g * 65536;
    float acc = (g == 0) ? gb[c] : ((g == 2) ? gb[512 + c] : 0.f);
#pragma unroll 8
    for (int k = 0; k < 256; k++) {
        acc += sx[k] * Wx[k * 256 + c];
        acc += ss[k] * Wg[k * 256 + c];
        acc += sc[k] * Wh[k * 256 + c];
    }
    float2 r = blk_reduce2(acc, acc * acc);
    float mean = r.x * (1.f / 256.f);
    float sd2 = fmaxf(r.y - 256.f * mean * mean, 0.f);
    float invs = 1.f / (sqrtf(sd2 * (1.f / 255.f)) + EPSV);
    int lnrow = (g == 0) ? 6 : ((g == 1) ? 9 : 7);
    float y = ln_a[lnrow * 256 + c] * (acc - mean) * invs + ln_b[lnrow * 256 + c];
    if (g == 1) y += gb[256 + c];
    float sg = sigf(y);
    if (g == 0) g_gd[b * 256 + c] = sg;
    else if (g == 1) g_gi[b * 256 + c] = sg;
    else g_go[b * 256 + c] = sg;
}

// ---------------- per-batch biases: Bd = dh@Wd_g ; Bfx = dh@gWx3 ----------------
__global__ void bd_k(const float* __restrict__ dh, const float* __restrict__ Wd_g) {
    int b = blockIdx.x, g = blockIdx.y, c = threadIdx.x;
    __shared__ float sx[256];
    sx[c] = dh[b * 256 + c];
    __syncthreads();
    const float* W = Wd_g + g * 65536;
    float acc = 0.f;
#pragma unroll 8
    for (int k = 0; k < 256; k++) acc += sx[k] * W[k * 256 + c];
    g_Bd[b * 1536 + g * 256 + c] = acc;
}
__global__ void bfx_k(const float* __restrict__ dh, const float* __restrict__ gWx) {
    int b = blockIdx.x, c = threadIdx.x;
    __shared__ float sx[256];
    sx[c] = dh[b * 256 + c];
    __syncthreads();
    const float* W = gWx + 3 * 65536;
    float acc = 0.f;
#pragma unroll 8
    for (int k = 0; k < 256; k++) acc += sx[k] * W[k * 256 + c];
    g_Bfx[b * 256 + c] = acc;
}

// ---------------- layer-invariant: tln = tanh(ln(se @ gWg3)) ----------------
__global__ void tln_k(const float* __restrict__ se, const float* __restrict__ gWg,
                      const float* __restrict__ ln_a, const float* __restrict__ ln_b) {
    int b = blockIdx.x, c = threadIdx.x;
    __shared__ float ss[256];
    ss[c] = se[b * 256 + c];
    __syncthreads();
    const float* W = gWg + 3 * 65536;
    float acc = 0.f;
#pragma unroll 8
    for (int k = 0; k < 256; k++) acc += ss[k] * W[k * 256 + c];
    float2 r = blk_reduce2(acc, acc * acc);
    float mean = r.x * (1.f / 256.f);
    float sd2 = fmaxf(r.y - 256.f * mean * mean, 0.f);
    float invs = 1.f / (sqrtf(sd2 * (1.f / 255.f)) + EPSV);
    float y = ln_a[10 * 256 + c] * (acc - mean) * invs + ln_b[10 * 256 + c];
    g_tln[b * 256 + c] = tanhf(y);
}

// ---------------- gf: LN + sigmoid + mask offset ----------------
__global__ void gf_ln_k(const float* __restrict__ GFp, const float* __restrict__ mask,
                        const float* __restrict__ ln_a, const float* __restrict__ ln_b) {
    int n = blockIdx.x, c = threadIdx.x;
    float x = GFp[(size_t)n * 256 + c];
    float2 r = blk_reduce2(x, x * x);
    float mean = r.x * (1.f / 256.f);
    float sd2 = fmaxf(r.y - 256.f * mean * mean, 0.f);
    float invs = 1.f / (sqrtf(sd2 * (1.f / 255.f)) + EPSV);
    float y = ln_a[8 * 256 + c] * (x - mean) * invs + ln_b[8 * 256 + c];
    float msm = mask[n] * 1e25f - 1e25f;
    g_GF[(size_t)n * 256 + c] = sigf(y) + msm;
}

// ---------------- score exp-sum over L (partials) + finalize dc/dh ----------------
__global__ void score_part_k(const float* __restrict__ Cc) {
    int b = blockIdx.x, s = blockIdx.y, c = threadIdx.x;
    float s1 = 0.f, s2 = 0.f;
    int rbase = (b << 10) + s * 128;
    for (int j = 0; j < 128; j++) {
        size_t idx = (size_t)(rbase + j) * 256 + c;
        float e = __expf(g_GF[idx]);
        s1 += e;
        s2 += e * Cc[idx];
    }
    g_p1[(b * 8 + s) * 256 + c] = s1;
    g_p2[(b * 8 + s) * 256 + c] = s2;
}
__global__ void score_fin_k(const float* __restrict__ dcOld, float* __restrict__ dhN,
                            float* __restrict__ dcN) {
    int b = blockIdx.x, c = threadIdx.x;
    int i = b * 256 + c;
    float S1 = 0.f, S2 = 0.f;
#pragma unroll
    for (int s = 0; s < 8; s++) {
        S1 += g_p1[(b * 8 + s) * 256 + c];
        S2 += g_p2[(b * 8 + s) * 256 + c];
    }
    float ed = __expf(g_gd[i]);
    float ei = __expf(g_gi[i]);
    float den = S1 + ed + ei;
    float dcn = (S2 + ed * dcOld[i] + ei * g_tln[i]) / den;
    dcN[i] = dcn;
    dhN[i] = g_go[i] * tanhf(dcn);
}

// ---------------- main epilogue: 6-gate LN + sigmoid + 5-softmax + state update ----------------
__global__ void gates_epi_k(const float* __restrict__ Cc, const float* __restrict__ dcOld,
                            const float* __restrict__ mask, const float* __restrict__ ln_a,
                            const float* __restrict__ ln_b, float* __restrict__ Hn,
                            float* __restrict__ Cn) {
    __shared__ float sP[6][256];
    __shared__ float sMean[6], sInv[6];
    int n = blockIdx.x, tid = threadIdx.x;
    size_t base = (size_t)n * 1536;
#pragma unroll
    for (int g = 0; g < 6; g++) sP[g][tid] = g_PRE[base + g * 256 + tid];
    __syncthreads();
    int w = tid >> 5, lane = tid & 31;
    if (w < 6) {
        float s = 0.f, q = 0.f;
#pragma unroll
        for (int j = 0; j < 8; j++) {
            float v = sP[w][lane + j * 32];
            s += v;
            q += v * v;
        }
#pragma unroll
        for (int o = 16; o; o >>= 1) {
            s += __shfl_xor_sync(0xffffffffu, s, o);
            q += __shfl_xor_sync(0xffffffffu, q, o);
        }
        if (lane == 0) {
            float mean = s * (1.f / 256.f);
            float sd2 = fmaxf(q - 256.f * mean * mean, 0.f);
            sMean[w] = mean;
            sInv[w] = 1.f / (sqrtf(sd2 * (1.f / 255.f)) + EPSV);
        }
    }
    __syncthreads();
    int c = tid;
    float sgm[6];
#pragma unroll
    for (int g = 0; g < 6; g++) {
        float y = ln_a[g * 256 + c] * (sP[g][c] - sMean[g]) * sInv[g] + ln_b[g * 256 + c];
        sgm[g] = sigf(y);
    }
    float e[5], es = 0.f;
#pragma unroll
    for (int g = 0; g < 5; g++) { e[g] = __expf(sgm[g]); es += e[g]; }
    float inv = 1.f / es;
    int l = n & 1023, b = n >> 10;
    float mk = mask[n];
    float cb = (l > 0) ? Cc[(size_t)(n - 1) * 256 + c] : 0.f;
    float ca = (l < 1023) ? Cc[(size_t)(n + 1) * 256 + c] : 0.f;
    float ccur = Cc[(size_t)n * 256 + c];
    float tdc = dcOld[b * 256 + c] * mk;
    float cnew = (cb * e[0] + ca * e[1] + g_emb[(size_t)n * 256 + c] * e[2] + tdc * e[3] + ccur * e[4]) * inv;
    float hnew = sgm[5] * tanhf(cnew);
    Hn[(size_t)n * 256 + c] = hnew * mk;
    Cn[(size_t)n * 256 + c] = cnew * mk;
}

// ---------------- host orchestration ----------------
extern "C" void kernel_launch(void* const* d_in, const int* in_sizes, int n_in,
                              void* d_out, int out_size) {
    const float* word = (const float*)d_in[0];
    const float* se   = (const float*)d_in[1];
    const float* mask = (const float*)d_in[2];
    const float* h0   = (const float*)d_in[3];
    const float* c0   = (const float*)d_in[4];
    const float* Wx_g = (const float*)d_in[5];
    const float* Wh_g = (const float*)d_in[6];
    const float* Wi_g = (const float*)d_in[7];
    const float* Wd_g = (const float*)d_in[8];
    const float* b_g  = (const float*)d_in[9];
    const float* gWx  = (const float*)d_in[10];
    const float* gWh  = (const float*)d_in[11];
    const float* gWg  = (const float*)d_in[12];
    const float* gb   = (const float*)d_in[13];
    const float* ln_a = (const float*)d_in[14];
    const float* ln_b = (const float*)d_in[15];
    float* out = (float*)d_out;

    float *ph, *pc, *pemb, *pE, *pPRE, *pGFp, *pWcat, *pWxp, *pdh, *pdc, *pcomb, *pcp, *pBd, *pBfx;
    cudaGetSymbolAddress((void**)&ph,   g_h);
    cudaGetSymbolAddress((void**)&pc,   g_c);
    cudaGetSymbolAddress((void**)&pemb, g_emb);
    cudaGetSymbolAddress((void**)&pE,   g_E);
    cudaGetSymbolAddress((void**)&pPRE, g_PRE);
    cudaGetSymbolAddress((void**)&pGFp, g_GFp);
    cudaGetSymbolAddress((void**)&pWcat, g_Wcat);
    cudaGetSymbolAddress((void**)&pWxp, g_Wxp);
    cudaGetSymbolAddress((void**)&pdh,  g_dh);
    cudaGetSymbolAddress((void**)&pdc,  g_dc);
    cudaGetSymbolAddress((void**)&pcomb, g_comb);
    cudaGetSymbolAddress((void**)&pcp,  g_cp);
    cudaGetSymbolAddress((void**)&pBd,  g_Bd);
    cudaGetSymbolAddress((void**)&pBfx, g_Bfx);

    const int SB = BBATCH * HDIM;

    // prep + initial means
    prep_k<<<NH / 1024, 256>>>(word, h0, c0, mask, pemb, ph, pc);
    colpart_k<<<dim3(32, 8), 256>>>(ph, pcp);
    colfin_k<<<32, 256>>>(pcp, pdh);
    colpart_k<<<dim3(32, 8), 256>>>(pc, pcp);
    colfin_k<<<32, 256>>>(pcp, pdc);

    // packing + layer-invariants
    pack_wcat_k<<<4608, 256>>>(Wh_g, Wi_g);
    pack_wx_k<<<1536, 256>>>(Wx_g);
    tln_k<<<32, 256>>>(se, gWg, ln_a, ln_b);
    gemm_k<false><<<dim3(12, 256), 256>>>(pemb, pWxp, nullptr, nullptr, nullptr, mask, pE, 1536, 256);

    for (int layer = 0; layer < 4; ++layer) {
        int cur = layer & 1, nxt = 1 - cur;
        float* hc = ph + (size_t)cur * NH;
        float* hn = ph + (size_t)nxt * NH;
        float* cc = pc + (size_t)cur * NH;
        float* cn = pc + (size_t)nxt * NH;
        float* dhc = pdh + cur * SB;
        float* dhn = pdh + nxt * SB;
        float* dcc = pdc + cur * SB;
        float* dcn = pdc + nxt * SB;
        float* htarget = (layer == 3) ? out : hn;

        colpart_k<<<dim3(32, 8), 256>>>(hc, pcp);
        colfin_k<<<32, 256>>>(pcp, pcomb);

        small_gates_k<<<dim3(32, 3), 256>>>(dhc, se, pcomb, gWx, gWg, gWh, gb, ln_a, ln_b);
        bd_k<<<dim3(32, 6), 256>>>(dhc, Wd_g);
        bfx_k<<<32, 256>>>(dhc, gWx);

        // gf path
        gemm_k<false><<<dim3(2, 256), 256>>>(hc, gWh + 3 * 65536, nullptr, gb + 768, pBfx, mask, pGFp, 256, 256);
        gf_ln_k<<<NROWS, 256>>>(pGFp, mask, ln_a, ln_b);
        score_part_k<<<dim3(32, 8), 256>>>(cc);
        score_fin_k<<<32, 256>>>(dcc, dhn, dcn);

        // main pre-activation GEMM (3-tap conv over h) + epilogue
        gemm_k<true><<<dim3(12, 256), 256>>>(hc, pWcat, pE, b_g, pBd, mask, pPRE, 1536, 768);
        gates_epi_k<<<NROWS, 256>>>(cc, dcc, mask, ln_a, ln_b, htarget, cn);
    }
}

// round 6
// speedup vs baseline: 1.3691x; 1.3691x over previous
#include <cuda_runtime.h>
#include <cuda_bf16.h>
#include <math.h>
#include <stdint.h>

#define BBATCH 32
#define LSEQ   1024
#define HDIM   256
#define NROWS  (BBATCH * LSEQ)      // 32768
#define NH     (NROWS * HDIM)       // 8388608
#define EPSV   1e-3f

typedef unsigned long long ull;

// ---------------- scratch (__device__ globals; allocation is forbidden) ----------------
__device__ float g_h[2][NH];
__device__ float g_c[2][NH];
__device__ float g_emb[NH];
__device__ float g_E[NROWS * 1536];
__device__ float g_PRE[NROWS * 1536];
__device__ float g_GFp[NH];
__device__ float g_GF[NH];
__device__ float g_dh[2][BBATCH * HDIM];
__device__ float g_dc[2][BBATCH * HDIM];
__device__ float g_comb[BBATCH * HDIM];
__device__ float g_gd[BBATCH * HDIM];
__device__ float g_gi[BBATCH * HDIM];
__device__ float g_go[BBATCH * HDIM];
__device__ float g_tln[BBATCH * HDIM];
__device__ float g_Bfx[BBATCH * HDIM];
__device__ float g_Bd[BBATCH * 1536];
__device__ float g_p1[BBATCH * 8 * HDIM];
__device__ float g_p2[BBATCH * 8 * HDIM];
__device__ float g_cp[BBATCH * 8 * HDIM];

// bf16 split operands
__device__ __nv_bfloat16 g_Whi[1536 * 768];   // main weights, [n][k] (B operand layout)
__device__ __nv_bfloat16 g_Wlo[1536 * 768];
__device__ __nv_bfloat16 g_Wxhi[1536 * 256];  // Wx packed transposed
__device__ __nv_bfloat16 g_Wxlo[1536 * 256];
__device__ __nv_bfloat16 g_gfhi[256 * 256];   // gWh[3] transposed
__device__ __nv_bfloat16 g_gflo[256 * 256];
__device__ __nv_bfloat16 g_hhi[NH];
__device__ __nv_bfloat16 g_hlo[NH];
__device__ __nv_bfloat16 g_ehi[NH];
__device__ __nv_bfloat16 g_elo[NH];

// ---------------- low-level helpers ----------------
__device__ __forceinline__ uint32_t smem_to_u32(const void* smem_ptr) {
    uint32_t addr;
    asm("{ .reg .u64 tmp; cvta.to.shared.u64 tmp, %1; cvt.u32.u64 %0, tmp; }"
        : "=r"(addr) : "l"(smem_ptr));
    return addr;
}
__device__ __forceinline__ uint32_t swz(uint32_t off) { return off ^ ((off >> 3) & 0x70); }

__device__ __forceinline__ void cpasync16(uint32_t dst, const void* src, int sz) {
    asm volatile("cp.async.cg.shared.global [%0], [%1], 16, %2;"
                 :: "r"(dst), "l"(src), "r"(sz) : "memory");
}
__device__ __forceinline__ void cp_commit() {
    asm volatile("cp.async.commit_group;" ::: "memory");
}
__device__ __forceinline__ void cp_wait2() {
    asm volatile("cp.async.wait_group 2;" ::: "memory");
}
__device__ __forceinline__ void ldsm4(uint32_t& r0, uint32_t& r1, uint32_t& r2, uint32_t& r3,
                                      uint32_t addr) {
    asm volatile("ldmatrix.sync.aligned.m8n8.x4.shared.b16 {%0,%1,%2,%3}, [%4];"
                 : "=r"(r0), "=r"(r1), "=r"(r2), "=r"(r3) : "r"(addr));
}
__device__ __forceinline__ void mma16816(float* c, const uint32_t* a, const uint32_t* b) {
    asm volatile(
        "mma.sync.aligned.m16n8k16.row.col.f32.bf16.bf16.f32 "
        "{%0,%1,%2,%3}, {%4,%5,%6,%7}, {%8,%9}, {%0,%1,%2,%3};"
        : "+f"(c[0]), "+f"(c[1]), "+f"(c[2]), "+f"(c[3])
        : "r"(a[0]), "r"(a[1]), "r"(a[2]), "r"(a[3]), "r"(b[0]), "r"(b[1]));
}

__device__ __forceinline__ float sigf(float x) { return 1.f / (1.f + __expf(-x)); }

__device__ __forceinline__ float2 blk_reduce2(float a, float b) {
    __shared__ float sA[8], sB[8];
    int lane = threadIdx.x & 31, w = threadIdx.x >> 5;
#pragma unroll
    for (int o = 16; o; o >>= 1) {
        a += __shfl_xor_sync(0xffffffffu, a, o);
        b += __shfl_xor_sync(0xffffffffu, b, o);
    }
    __syncthreads();
    if (lane == 0) { sA[w] = a; sB[w] = b; }
    __syncthreads();
    float ra = 0.f, rb = 0.f;
#pragma unroll
    for (int i = 0; i < 8; i++) { ra += sA[i]; rb += sB[i]; }
    return make_float2(ra, rb);
}

// ---------------- prep: masked inputs ----------------
__global__ void prep_k(const float* __restrict__ word, const float* __restrict__ h0,
                       const float* __restrict__ c0, const float* __restrict__ mask,
                       float* __restrict__ emb, float* __restrict__ h, float* __restrict__ c) {
    int i4 = blockIdx.x * blockDim.x + threadIdx.x;
    if (i4 >= NH / 4) return;
    float m = mask[i4 >> 6];
    float4 w = ((const float4*)word)[i4];
    float4 a = ((const float4*)h0)[i4];
    float4 b = ((const float4*)c0)[i4];
    w.x *= m; w.y *= m; w.z *= m; w.w *= m;
    a.x *= m; a.y *= m; a.z *= m; a.w *= m;
    b.x *= m; b.y *= m; b.z *= m; b.w *= m;
    ((float4*)emb)[i4] = w;
    ((float4*)h)[i4]   = a;
    ((float4*)c)[i4]   = b;
}

// ---------------- column mean over L (two-stage) ----------------
__global__ void colpart_k(const float* __restrict__ X, float* __restrict__ part) {
    int b = blockIdx.x, s = blockIdx.y, c = threadIdx.x;
    float acc = 0.f;
    int rbase = (b << 10) + s * 128;
#pragma unroll 4
    for (int j = 0; j < 128; j++) acc += X[(size_t)(rbase + j) * HDIM + c];
    part[(b * 8 + s) * HDIM + c] = acc;
}
__global__ void colfin_k(const float* __restrict__ part, float* __restrict__ out) {
    int b = blockIdx.x, c = threadIdx.x;
    float a = 0.f;
#pragma unroll
    for (int s = 0; s < 8; s++) a += part[(b * 8 + s) * HDIM + c];
    out[b * HDIM + c] = a * (1.f / 1024.f);
}

// ---------------- bf16 split packing ----------------
__device__ __forceinline__ void bf_split(float v, __nv_bfloat16& h, __nv_bfloat16& l) {
    h = __float2bfloat16(v);
    l = __float2bfloat16(v - __bfloat162float(h));
}
__global__ void packW_k(const float* __restrict__ Wh_g, const float* __restrict__ Wi_g) {
    int idx = blockIdx.x * 256 + threadIdx.x;            // 1536*768
    if (idx >= 1536 * 768) return;
    int n = idx / 768, kk = idx - n * 768;
    int g = n >> 8, c = n & 255;
    float v = (kk < 512) ? Wh_g[g * 131072 + kk * 256 + c]
                         : Wi_g[g * 65536 + (kk - 512) * 256 + c];
    bf_split(v, g_Whi[idx], g_Wlo[idx]);
}
__global__ void packWx_k(const float* __restrict__ Wx_g) {
    int idx = blockIdx.x * 256 + threadIdx.x;            // 1536*256
    if (idx >= 1536 * 256) return;
    int n = idx / 256, k = idx - n * 256;
    int g = n >> 8, c = n & 255;
    bf_split(Wx_g[g * 65536 + k * 256 + c], g_Wxhi[idx], g_Wxlo[idx]);
}
__global__ void packGf_k(const float* __restrict__ gWh) {
    int idx = blockIdx.x * 256 + threadIdx.x;            // 256*256
    if (idx >= 256 * 256) return;
    int n = idx / 256, k = idx - n * 256;
    bf_split(gWh[3 * 65536 + k * 256 + n], g_gfhi[idx], g_gflo[idx]);
}
__global__ void split_k(const float4* __restrict__ src, uint2* __restrict__ hi,
                        uint2* __restrict__ lo) {
    int i = blockIdx.x * blockDim.x + threadIdx.x;       // NH/4
    float4 v = src[i];
    __nv_bfloat16 h0, h1, h2, h3, l0, l1, l2, l3;
    bf_split(v.x, h0, l0); bf_split(v.y, h1, l1);
    bf_split(v.z, h2, l2); bf_split(v.w, h3, l3);
    uint2 H, L;
    H.x = ((uint32_t)__bfloat16_as_ushort(h1) << 16) | __bfloat16_as_ushort(h0);
    H.y = ((uint32_t)__bfloat16_as_ushort(h3) << 16) | __bfloat16_as_ushort(h2);
    L.x = ((uint32_t)__bfloat16_as_ushort(l1) << 16) | __bfloat16_as_ushort(l0);
    L.y = ((uint32_t)__bfloat16_as_ushort(l3) << 16) | __bfloat16_as_ushort(l2);
    hi[i] = H; lo[i] = L;
}

// ---------------- bf16-split GEMM via legacy mma.sync (HMMA) ----------------
// C[NROWS x cols] = sum_{3 splits} A @ B^T (+Cadd +colbias +mask*pbias)
// CTA 128x128, K-stage 64 (128B rows, SW128), 3-stage cp.async pipeline.
// A K-major bf16 (conv taps when TAPS); B [n][k] bf16.
#define SMEM_MMA (3 * 32768)
template <bool TAPS>
__global__ __launch_bounds__(256) void gemm_mma_k(
    const __nv_bfloat16* __restrict__ Ahi, const __nv_bfloat16* __restrict__ Alo,
    const __nv_bfloat16* __restrict__ Bhi, const __nv_bfloat16* __restrict__ Blo,
    const float* __restrict__ Cadd, const float* __restrict__ colbias,
    const float* __restrict__ pbias, const float* __restrict__ mask,
    float* __restrict__ C, int cols, int K) {
    extern __shared__ char sm[];
    const uint32_t sbase = smem_to_u32(sm);
    const int tid = threadIdx.x, wid = tid >> 5, lane = tid & 31;
    const int wm = wid >> 2, wn = wid & 3;
    const int rowBase = blockIdx.y * 128;
    const int colBase = blockIdx.x * 128;
    const int KC = K >> 6;             // 64-elem chunks per split
    const int NC = 3 * KC;

    float acc[4][4][4];
#pragma unroll
    for (int a = 0; a < 4; a++)
#pragma unroll
        for (int b = 0; b < 4; b++)
#pragma unroll
            for (int d = 0; d < 4; d++) acc[a][b][d] = 0.f;

    auto issue = [&](int cc) {
        const int buf = cc % 3;
        const int split = cc / KC;
        const int kc = cc - split * KC;
        const __nv_bfloat16* Ab = (split == 1) ? Alo : Ahi;
        const __nv_bfloat16* Bb = (split == 2) ? Blo : Bhi;
        const int tap = TAPS ? (kc >> 2) : 2;
        const int chA = TAPS ? ((kc & 3) << 6) : (kc << 6);
        const int kB = kc << 6;
        const int d = (tap == 0) ? -1 : ((tap == 1) ? 1 : 0);
        const uint32_t sA = sbase + buf * 32768;
        const uint32_t sB = sA + 16384;
#pragma unroll
        for (int i = 0; i < 4; ++i) {
            int idx = tid + i * 256;                  // 0..1023
            int r = idx >> 3, g = idx & 7;
            int grow = rowBase + r, l = grow & 1023;
            bool ok = (tap == 0) ? (l > 0) : ((tap == 1) ? (l < 1023) : true);
            const __nv_bfloat16* src = Ab + (size_t)(grow + (ok ? d : 0)) * 256 + chA + g * 8;
            cpasync16(sA + swz(r * 128 + g * 16), src, ok ? 16 : 0);
        }
#pragma unroll
        for (int i = 0; i < 4; ++i) {
            int idx = tid + i * 256;
            int n = idx >> 3, g = idx & 7;
            const __nv_bfloat16* src = Bb + (size_t)(colBase + n) * K + kB + g * 8;
            cpasync16(sB + swz(n * 128 + g * 16), src, 16);
        }
    };

    issue(0); cp_commit();
    issue(1); cp_commit();

    const int aRow = wm * 64 + (lane & 15);
    const int bRow = wn * 32 + (lane & 15);
    const int gSel = lane >> 4;

    for (int cc = 0; cc < NC; ++cc) {
        if (cc + 2 < NC) issue(cc + 2);
        cp_commit();
        cp_wait2();
        __syncthreads();
        const int buf = cc % 3;
        const uint32_t sA = sbase + buf * 32768;
        const uint32_t sB = sA + 16384;
#pragma unroll
        for (int ks = 0; ks < 4; ++ks) {
            uint32_t aT[4][4], bT[4][2];
            const int g = ks * 2 + gSel;
#pragma unroll
            for (int mt = 0; mt < 4; ++mt) {
                uint32_t addr = sA + swz((aRow + mt * 16) * 128 + g * 16);
                ldsm4(aT[mt][0], aT[mt][1], aT[mt][2], aT[mt][3], addr);
            }
#pragma unroll
            for (int bt = 0; bt < 2; ++bt) {
                uint32_t r0, r1, r2, r3;
                uint32_t addr = sB + swz((bRow + bt * 16) * 128 + g * 16);
                ldsm4(r0, r1, r2, r3, addr);
                bT[bt * 2 + 0][0] = r0; bT[bt * 2 + 0][1] = r2;
                bT[bt * 2 + 1][0] = r1; bT[bt * 2 + 1][1] = r3;
            }
#pragma unroll
            for (int mt = 0; mt < 4; ++mt)
#pragma unroll
                for (int nt = 0; nt < 4; ++nt)
                    mma16816(acc[mt][nt], aT[mt], bT[nt]);
        }
        __syncthreads();
    }

    // epilogue: direct frag stores with fused adds
#pragma unroll
    for (int mt = 0; mt < 4; ++mt) {
#pragma unroll
        for (int i = 0; i < 2; ++i) {
            int r = rowBase + wm * 64 + mt * 16 + (lane >> 2) + i * 8;
            float mk = mask[r];
            int bb = r >> 10;
            size_t rowoff = (size_t)r * cols;
#pragma unroll
            for (int nt = 0; nt < 4; ++nt) {
                int ccol = colBase + wn * 32 + nt * 8 + (lane & 3) * 2;
                float2 v = make_float2(acc[mt][nt][2 * i], acc[mt][nt][2 * i + 1]);
                if (Cadd) {
                    float2 a = *(const float2*)(Cadd + rowoff + ccol);
                    v.x += a.x; v.y += a.y;
                }
                if (colbias) {
                    float2 a = *(const float2*)(colbias + ccol);
                    v.x += a.x; v.y += a.y;
                }
                if (pbias) {
                    float2 p = *(const float2*)(pbias + (size_t)bb * cols + ccol);
                    v.x += mk * p.x; v.y += mk * p.y;
                }
                *(float2*)(C + rowoff + ccol) = v;
            }
        }
    }
}

// ---------------- sentence-level gates: gd / gi / go ----------------
__global__ void small_gates_k(const float* __restrict__ dh, const float* __restrict__ se,
                              const float* __restrict__ comb, const float* __restrict__ gWx,
                              const float* __restrict__ gWg, const float* __restrict__ gWh,
                              const float* __restrict__ gb, const float* __restrict__ ln_a,
                              const float* __restrict__ ln_b) {
    int b = blockIdx.x, g = blockIdx.y, c = threadIdx.x;
    __shared__ float sx[256], ss[256], sc[256];
    sx[c] = dh[b * 256 + c];
    ss[c] = se[b * 256 + c];
    sc[c] = comb[b * 256 + c];
    __syncthreads();
    const float* Wx = gWx + g * 65536;
    const float* Wg = gWg + g * 65536;
    const float* Wh = gWh + g * 65536;
    float acc = (g == 0) ? gb[c] : ((g == 2) ? gb[512 + c] : 0.f);
#pragma unroll 8
    for (int k = 0; k < 256; k++) {
        acc += sx[k] * Wx[k * 256 + c];
        acc += ss[k] * Wg[k * 256 + c];
        acc += sc[k] * Wh[k * 256 + c];
    }
    float2 r = blk_reduce2(acc, acc * acc);
    float mean = r.x * (1.f / 256.f);
    float sd2 = fmaxf(r.y - 256.f * mean * mean, 0.f);
    float invs = 1.f / (sqrtf(sd2 * (1.f / 255.f)) + EPSV);
    int lnrow = (g == 0) ? 6 : ((g == 1) ? 9 : 7);
    float y = ln_a[lnrow * 256 + c] * (acc - mean) * invs + ln_b[lnrow * 256 + c];
    if (g == 1) y += gb[256 + c];
    float sg = sigf(y);
    if (g == 0) g_gd[b * 256 + c] = sg;
    else if (g == 1) g_gi[b * 256 + c] = sg;
    else g_go[b * 256 + c] = sg;
}

// ---------------- per-batch biases: Bd = dh@Wd_g ; Bfx = dh@gWx3 ----------------
__global__ void bd_k(const float* __restrict__ dh, const float* __restrict__ Wd_g) {
    int b = blockIdx.x, g = blockIdx.y, c = threadIdx.x;
    __shared__ float sx[256];
    sx[c] = dh[b * 256 + c];
    __syncthreads();
    const float* W = Wd_g + g * 65536;
    float acc = 0.f;
#pragma unroll 8
    for (int k = 0; k < 256; k++) acc += sx[k] * W[k * 256 + c];
    g_Bd[b * 1536 + g * 256 + c] = acc;
}
__global__ void bfx_k(const float* __restrict__ dh, const float* __restrict__ gWx) {
    int b = blockIdx.x, c = threadIdx.x;
    __shared__ float sx[256];
    sx[c] = dh[b * 256 + c];
    __syncthreads();
    const float* W = gWx + 3 * 65536;
    float acc = 0.f;
#pragma unroll 8
    for (int k = 0; k < 256; k++) acc += sx[k] * W[k * 256 + c];
    g_Bfx[b * 256 + c] = acc;
}

// ---------------- layer-invariant: tln = tanh(ln(se @ gWg3)) ----------------
__global__ void tln_k(const float* __restrict__ se, const float* __restrict__ gWg,
                      const float* __restrict__ ln_a, const float* __restrict__ ln_b) {
    int b = blockIdx.x, c = threadIdx.x;
    __shared__ float ss[256];
    ss[c] = se[b * 256 + c];
    __syncthreads();
    const float* W = gWg + 3 * 65536;
    float acc = 0.f;
#pragma unroll 8
    for (int k = 0; k < 256; k++) acc += ss[k] * W[k * 256 + c];
    float2 r = blk_reduce2(acc, acc * acc);
    float mean = r.x * (1.f / 256.f);
    float sd2 = fmaxf(r.y - 256.f * mean * mean, 0.f);
    float invs = 1.f / (sqrtf(sd2 * (1.f / 255.f)) + EPSV);
    float y = ln_a[10 * 256 + c] * (acc - mean) * invs + ln_b[10 * 256 + c];
    g_tln[b * 256 + c] = tanhf(y);
}

// ---------------- gf: LN + sigmoid + mask offset ----------------
__global__ void gf_ln_k(const float* __restrict__ GFp, const float* __restrict__ mask,
                        const float* __restrict__ ln_a, const float* __restrict__ ln_b) {
    int n = blockIdx.x, c = threadIdx.x;
    float x = GFp[(size_t)n * 256 + c];
    float2 r = blk_reduce2(x, x * x);
    float mean = r.x * (1.f / 256.f);
    float sd2 = fmaxf(r.y - 256.f * mean * mean, 0.f);
    float invs = 1.f / (sqrtf(sd2 * (1.f / 255.f)) + EPSV);
    float y = ln_a[8 * 256 + c] * (x - mean) * invs + ln_b[8 * 256 + c];
    float msm = mask[n] * 1e25f - 1e25f;
    g_GF[(size_t)n * 256 + c] = sigf(y) + msm;
}

// ---------------- score exp-sum over L (partials) + finalize dc/dh ----------------
__global__ void score_part_k(const float* __restrict__ Cc) {
    int b = blockIdx.x, s = blockIdx.y, c = threadIdx.x;
    float s1 = 0.f, s2 = 0.f;
    int rbase = (b << 10) + s * 128;
    for (int j = 0; j < 128; j++) {
        size_t idx = (size_t)(rbase + j) * 256 + c;
        float e = __expf(g_GF[idx]);
        s1 += e;
        s2 += e * Cc[idx];
    }
    g_p1[(b * 8 + s) * 256 + c] = s1;
    g_p2[(b * 8 + s) * 256 + c] = s2;
}
__global__ void score_fin_k(const float* __restrict__ dcOld, float* __restrict__ dhN,
                            float* __restrict__ dcN) {
    int b = blockIdx.x, c = threadIdx.x;
    int i = b * 256 + c;
    float S1 = 0.f, S2 = 0.f;
#pragma unroll
    for (int s = 0; s < 8; s++) {
        S1 += g_p1[(b * 8 + s) * 256 + c];
        S2 += g_p2[(b * 8 + s) * 256 + c];
    }
    float ed = __expf(g_gd[i]);
    float ei = __expf(g_gi[i]);
    float den = S1 + ed + ei;
    float dcn = (S2 + ed * dcOld[i] + ei * g_tln[i]) / den;
    dcN[i] = dcn;
    dhN[i] = g_go[i] * tanhf(dcn);
}

// ---------------- main epilogue: 6-gate LN + sigmoid + 5-softmax + state update ----------------
__global__ void gates_epi_k(const float* __restrict__ Cc, const float* __restrict__ dcOld,
                            const float* __restrict__ mask, const float* __restrict__ ln_a,
                            const float* __restrict__ ln_b, float* __restrict__ Hn,
                            float* __restrict__ Cn) {
    __shared__ float sP[6][256];
    __shared__ float sMean[6], sInv[6];
    int n = blockIdx.x, tid = threadIdx.x;
    size_t base = (size_t)n * 1536;
#pragma unroll
    for (int g = 0; g < 6; g++) sP[g][tid] = g_PRE[base + g * 256 + tid];
    __syncthreads();
    int w = tid >> 5, lane = tid & 31;
    if (w < 6) {
        float s = 0.f, q = 0.f;
#pragma unroll
        for (int j = 0; j < 8; j++) {
            float v = sP[w][lane + j * 32];
            s += v;
            q += v * v;
        }
#pragma unroll
        for (int o = 16; o; o >>= 1) {
            s += __shfl_xor_sync(0xffffffffu, s, o);
            q += __shfl_xor_sync(0xffffffffu, q, o);
        }
        if (lane == 0) {
            float mean = s * (1.f / 256.f);
            float sd2 = fmaxf(q - 256.f * mean * mean, 0.f);
            sMean[w] = mean;
            sInv[w] = 1.f / (sqrtf(sd2 * (1.f / 255.f)) + EPSV);
        }
    }
    __syncthreads();
    int c = tid;
    float sgm[6];
#pragma unroll
    for (int g = 0; g < 6; g++) {
        float y = ln_a[g * 256 + c] * (sP[g][c] - sMean[g]) * sInv[g] + ln_b[g * 256 + c];
        sgm[g] = sigf(y);
    }
    float e[5], es = 0.f;
#pragma unroll
    for (int g = 0; g < 5; g++) { e[g] = __expf(sgm[g]); es += e[g]; }
    float inv = 1.f / es;
    int l = n & 1023, b = n >> 10;
    float mk = mask[n];
    float cb = (l > 0) ? Cc[(size_t)(n - 1) * 256 + c] : 0.f;
    float ca = (l < 1023) ? Cc[(size_t)(n + 1) * 256 + c] : 0.f;
    float ccur = Cc[(size_t)n * 256 + c];
    float tdc = dcOld[b * 256 + c] * mk;
    float cnew = (cb * e[0] + ca * e[1] + g_emb[(size_t)n * 256 + c] * e[2] + tdc * e[3] + ccur * e[4]) * inv;
    float hnew = sgm[5] * tanhf(cnew);
    Hn[(size_t)n * 256 + c] = hnew * mk;
    Cn[(size_t)n * 256 + c] = cnew * mk;
}

// ---------------- host orchestration ----------------
extern "C" void kernel_launch(void* const* d_in, const int* in_sizes, int n_in,
                              void* d_out, int out_size) {
    const float* word = (const float*)d_in[0];
    const float* se   = (const float*)d_in[1];
    const float* mask = (const float*)d_in[2];
    const float* h0   = (const float*)d_in[3];
    const float* c0   = (const float*)d_in[4];
    const float* Wx_g = (const float*)d_in[5];
    const float* Wh_g = (const float*)d_in[6];
    const float* Wi_g = (const float*)d_in[7];
    const float* Wd_g = (const float*)d_in[8];
    const float* b_g  = (const float*)d_in[9];
    const float* gWx  = (const float*)d_in[10];
    const float* gWh  = (const float*)d_in[11];
    const float* gWg  = (const float*)d_in[12];
    const float* gb   = (const float*)d_in[13];
    const float* ln_a = (const float*)d_in[14];
    const float* ln_b = (const float*)d_in[15];
    float* out = (float*)d_out;

    cudaFuncSetAttribute(gemm_mma_k<true>,  cudaFuncAttributeMaxDynamicSharedMemorySize, SMEM_MMA);
    cudaFuncSetAttribute(gemm_mma_k<false>, cudaFuncAttributeMaxDynamicSharedMemorySize, SMEM_MMA);

    float *ph, *pc, *pemb, *pE, *pPRE, *pGFp, *pdh, *pdc, *pcomb, *pcp, *pBd, *pBfx;
    __nv_bfloat16 *pWhi, *pWlo, *pWxhi, *pWxlo, *pgfhi, *pgflo, *phhi, *phlo, *pehi, *pelo;
    cudaGetSymbolAddress((void**)&ph,    g_h);
    cudaGetSymbolAddress((void**)&pc,    g_c);
    cudaGetSymbolAddress((void**)&pemb,  g_emb);
    cudaGetSymbolAddress((void**)&pE,    g_E);
    cudaGetSymbolAddress((void**)&pPRE,  g_PRE);
    cudaGetSymbolAddress((void**)&pGFp,  g_GFp);
    cudaGetSymbolAddress((void**)&pdh,   g_dh);
    cudaGetSymbolAddress((void**)&pdc,   g_dc);
    cudaGetSymbolAddress((void**)&pcomb, g_comb);
    cudaGetSymbolAddress((void**)&pcp,   g_cp);
    cudaGetSymbolAddress((void**)&pBd,   g_Bd);
    cudaGetSymbolAddress((void**)&pBfx,  g_Bfx);
    cudaGetSymbolAddress((void**)&pWhi,  g_Whi);
    cudaGetSymbolAddress((void**)&pWlo,  g_Wlo);
    cudaGetSymbolAddress((void**)&pWxhi, g_Wxhi);
    cudaGetSymbolAddress((void**)&pWxlo, g_Wxlo);
    cudaGetSymbolAddress((void**)&pgfhi, g_gfhi);
    cudaGetSymbolAddress((void**)&pgflo, g_gflo);
    cudaGetSymbolAddress((void**)&phhi,  g_hhi);
    cudaGetSymbolAddress((void**)&phlo,  g_hlo);
    cudaGetSymbolAddress((void**)&pehi,  g_ehi);
    cudaGetSymbolAddress((void**)&pelo,  g_elo);

    const int SB = BBATCH * HDIM;

    // prep + initial means
    prep_k<<<NH / 1024, 256>>>(word, h0, c0, mask, pemb, ph, pc);
    colpart_k<<<dim3(32, 8), 256>>>(ph, pcp);
    colfin_k<<<32, 256>>>(pcp, pdh);
    colpart_k<<<dim3(32, 8), 256>>>(pc, pcp);
    colfin_k<<<32, 256>>>(pcp, pdc);

    // bf16 packing + layer-invariants
    packW_k<<<4608, 256>>>(Wh_g, Wi_g);
    packWx_k<<<1536, 256>>>(Wx_g);
    packGf_k<<<256, 256>>>(gWh);
    split_k<<<NH / 4 / 256, 256>>>((const float4*)pemb, (uint2*)pehi, (uint2*)pelo);
    tln_k<<<32, 256>>>(se, gWg, ln_a, ln_b);
    gemm_mma_k<false><<<dim3(12, 256), 256, SMEM_MMA>>>(
        pehi, pelo, pWxhi, pWxlo, nullptr, nullptr, nullptr, mask, pE, 1536, 256);

    for (int layer = 0; layer < 4; ++layer) {
        int cur = layer & 1, nxt = 1 - cur;
        float* hc = ph + (size_t)cur * NH;
        float* hn = ph + (size_t)nxt * NH;
        float* cc = pc + (size_t)cur * NH;
        float* cn = pc + (size_t)nxt * NH;
        float* dhc = pdh + cur * SB;
        float* dhn = pdh + nxt * SB;
        float* dcc = pdc + cur * SB;
        float* dcn = pdc + nxt * SB;
        float* htarget = (layer == 3) ? out : hn;

        colpart_k<<<dim3(32, 8), 256>>>(hc, pcp);
        colfin_k<<<32, 256>>>(pcp, pcomb);

        small_gates_k<<<dim3(32, 3), 256>>>(dhc, se, pcomb, gWx, gWg, gWh, gb, ln_a, ln_b);
        bd_k<<<dim3(32, 6), 256>>>(dhc, Wd_g);
        bfx_k<<<32, 256>>>(dhc, gWx);

        // bf16 split of h for this layer's GEMMs
        split_k<<<NH / 4 / 256, 256>>>((const float4*)hc, (uint2*)phhi, (uint2*)phlo);

        // gf path (K=256, N=256)
        gemm_mma_k<false><<<dim3(2, 256), 256, SMEM_MMA>>>(
            phhi, phlo, pgfhi, pgflo, nullptr, gb + 768, pBfx, mask, pGFp, 256, 256);
        gf_ln_k<<<NROWS, 256>>>(pGFp, mask, ln_a, ln_b);
        score_part_k<<<dim3(32, 8), 256>>>(cc);
        score_fin_k<<<32, 256>>>(dcc, dhn, dcn);

        // main pre-activation GEMM (3-tap conv over h) + fused E/bias epilogue
        gemm_mma_k<true><<<dim3(12, 256), 256, SMEM_MMA>>>(
            phhi, phlo, pWhi, pWlo, pE, b_g, pBd, mask, pPRE, 1536, 768);
        gates_epi_k<<<NROWS, 256>>>(cc, dcc, mask, ln_a, ln_b, htarget, cn);
    }
}